// round 15
// baseline (speedup 1.0000x reference)
#include <cuda_runtime.h>

// ---- Problem constants -----------------------------------------------------
#define CC   128
#define HH   112
#define WW   112
#define HO   56
#define WO   56

// ---- Accurate logf (njuffa, max err 0.85089 ulp), fast-math-proof ----------
__device__ __forceinline__ float log_acc(float a) {
    int   e = (__float_as_int(a) - 0x3f2aaaab) & 0xff800000;
    float m = __int_as_float(__float_as_int(a) - e);
    float i = (float)e * 1.19209290e-7f;     // 2^-23
    m = m - 1.0f;
    float s = m * m;
    float r = -0.130310059f;
    float t =  0.140869141f;
    r = fmaf(r, s, -0.121483512f);
    t = fmaf(t, s,  0.139814854f);
    r = fmaf(r, s, -0.166846126f);
    t = fmaf(t, s,  0.200120345f);
    r = fmaf(r, s, -0.249996200f);
    r = fmaf(t, m, r);
    r = fmaf(r, m,  0.333331972f);
    r = fmaf(r, m, -0.500000000f);
    r = fmaf(r, s, m);
    r = fmaf(i, 0.693147182f, r);
    return r;
}

// bits -> uniform (JAX semantics) -> standard gumbel.
// f + 1e-20 >= 1e-20 holds bit-exactly for all representable f >= 0,
// so the reference's max(..., 1e-20) clamp is a no-op we drop.
__device__ __forceinline__ float gumbel_from_bits(unsigned bits) {
    float f = __uint_as_float((bits >> 9) | 0x3f800000u) - 1.0f;  // [0,1)
    float u = f + 1e-20f;
    return -log_acc(-log_acc(u));
}

// ---- Threefry-2x32, key (0,42), partitionable mode -------------------------
// Pipe-balanced round: the add runs as IMAD (x1*one + x0, one==1, runtime-
// opaque) on the FMA pipe; rotate stays SHF and xor stays LOP3 on the ALU
// pipe. Exact arithmetic (multiply by 1), only scheduling changes.
#define TF_RND(r) { x0 = x1 * one + x0;                                 \
                    x1 = __funnelshift_l(x1, x1, (r)) ^ x0; }

__global__ __launch_bounds__(224)
void tdgs_pool_kernel(const float* __restrict__ x,
                      const float* __restrict__ temperature,
                      float* __restrict__ out) {
    // Runtime-opaque 1 (threadIdx.z == 0 always, but ptxas cannot fold it):
    // forces the round-adds onto the fma pipe as IMAD.
    const unsigned one = 1u << threadIdx.z;

    const unsigned wo = threadIdx.x;                       // 0..55
    const unsigned ho = blockIdx.x * 4u + threadIdx.y;     // 0..55
    const unsigned c  = blockIdx.y;                        // 0..127
    const unsigned b  = blockIdx.z;                        // 0..31

    float tp = temperature[(c * HO + ho) * WO + wo];
    tp = fmaxf(tp, 0.0f) + 0.1f;

    const unsigned base = ((b * CC + c) * HH + 2u * ho) * WW + 2u * wo;
    const float2 a0 = *reinterpret_cast<const float2*>(x + base);
    const float2 a1 = *reinterpret_cast<const float2*>(x + base + WW);
    const float xs[4] = {a0.x, a0.y, a1.x, a1.y};

    const unsigned p   = ((b * CC + c) * HO + ho) * WO + wo;
    const unsigned ctr = 4u * p;

    float best = -__int_as_float(0x7f800000);  // -inf
    float sel  = 0.0f;

    #pragma unroll
    for (int j = 0; j < 4; j++) {
        const unsigned ks0 = 0u, ks1 = 42u, ks2 = 0x1BD11BDAu ^ 42u;
        unsigned x0 = ks0;                 // counter hi word = 0 (N < 2^32)
        unsigned x1 = (ctr + (unsigned)j) + ks1;
        TF_RND(13) TF_RND(15) TF_RND(26) TF_RND(6)
        x0 += ks1; x1 += ks2 + 1u;
        TF_RND(17) TF_RND(29) TF_RND(16) TF_RND(24)
        x0 += ks2; x1 += ks0 + 2u;
        TF_RND(13) TF_RND(15) TF_RND(26) TF_RND(6)
        x0 += ks0; x1 += ks1 + 3u;
        TF_RND(17) TF_RND(29) TF_RND(16) TF_RND(24)
        x0 += ks1; x1 += ks2 + 4u;
        TF_RND(13) TF_RND(15) TF_RND(26) TF_RND(6)
        x0 += ks2; x1 += ks0 + 5u;
        const unsigned bits = x0 ^ x1;     // partitionable xor-fold

        const float g = gumbel_from_bits(bits);
        const float v = __fdiv_rn(xs[j], tp) + g;
        if (v > best) { best = v; sel = xs[j]; }  // first-max wins ties
    }

    out[p] = sel;
}

extern "C" void kernel_launch(void* const* d_in, const int* in_sizes, int n_in,
                              void* d_out, int out_size) {
    const float* x    = (const float*)d_in[0];  // (32,128,112,112) f32
    const float* temp = (const float*)d_in[1];  // (128,56,56) f32
    float* out        = (float*)d_out;          // (32,128,56,56) f32
    (void)in_sizes; (void)n_in; (void)out_size;

    dim3 block(56, 4, 1);    // 224 threads
    dim3 grid(14, 128, 32);  // 14*4 = 56 = HO rows; c; b
    tdgs_pool_kernel<<<grid, block>>>(x, temp, out);
}

// round 16
// speedup vs baseline: 1.2677x; 1.2677x over previous
#include <cuda_runtime.h>

// ---- Problem constants -----------------------------------------------------
#define CC   128
#define HH   112
#define WW   112
#define HO   56
#define WO   56
#define P_TOT  12845056   // 32*128*56*56 output elements
#define HALF_P 6422528    // P_TOT/2: threads (each does batch b and b+16)
#define OFF2   25690112   // 16*128*112*112: float offset between paired batches

// ---- Accurate logf (njuffa, max err 0.85089 ulp), fast-math-proof ----------
__device__ __forceinline__ float log_acc(float a) {
    int   e = (__float_as_int(a) - 0x3f2aaaab) & 0xff800000;
    float m = __int_as_float(__float_as_int(a) - e);
    float i = (float)e * 1.19209290e-7f;     // 2^-23
    m = m - 1.0f;
    float s = m * m;
    float r = -0.130310059f;
    float t =  0.140869141f;
    r = fmaf(r, s, -0.121483512f);
    t = fmaf(t, s,  0.139814854f);
    r = fmaf(r, s, -0.166846126f);
    t = fmaf(t, s,  0.200120345f);
    r = fmaf(r, s, -0.249996200f);
    r = fmaf(t, m, r);
    r = fmaf(r, m,  0.333331972f);
    r = fmaf(r, m, -0.500000000f);
    r = fmaf(r, s, m);
    r = fmaf(i, 0.693147182f, r);
    return r;
}

// bits -> uniform (JAX semantics) -> standard gumbel
__device__ __forceinline__ float gumbel_from_bits(unsigned bits) {
    float f = __uint_as_float((bits >> 9) | 0x3f800000u) - 1.0f;  // [0,1)
    float u = fmaxf(f + 1e-20f, 1e-20f);
    return -log_acc(-log_acc(u));
}

// ---- Threefry-2x32, key (0,42), partitionable mode (verified R6 form) ------
#define TF_RND(r) { x0 += x1; x1 = __funnelshift_l(x1, x1, (r)); x1 ^= x0; }

__device__ __forceinline__ unsigned threefry_bits(unsigned lo) {
    const unsigned ks0 = 0u, ks1 = 42u, ks2 = 0x1BD11BDAu ^ 42u;
    unsigned x0 = ks0;           // counter hi word = 0 (N < 2^32)
    unsigned x1 = lo + ks1;
    TF_RND(13) TF_RND(15) TF_RND(26) TF_RND(6)
    x0 += ks1; x1 += ks2 + 1u;
    TF_RND(17) TF_RND(29) TF_RND(16) TF_RND(24)
    x0 += ks2; x1 += ks0 + 2u;
    TF_RND(13) TF_RND(15) TF_RND(26) TF_RND(6)
    x0 += ks0; x1 += ks1 + 3u;
    TF_RND(17) TF_RND(29) TF_RND(16) TF_RND(24)
    x0 += ks1; x1 += ks2 + 4u;
    TF_RND(13) TF_RND(15) TF_RND(26) TF_RND(6)
    x0 += ks2; x1 += ks0 + 5u;
    return x0 ^ x1;              // partitionable xor-fold
}

// ---- Kernel: one thread handles patches (b,...) and (b+16,...) --------------
// Both share temperature[(c,ho,wo)]; output indices t and t+HALF_P.
__global__ __launch_bounds__(256)
void tdgs_pool_kernel(const float* __restrict__ x,
                      const float* __restrict__ temperature,
                      float* __restrict__ out) {
    unsigned t = blockIdx.x * blockDim.x + threadIdx.x;
    if (t >= HALF_P) return;

    unsigned wo  = t % WO;
    unsigned tmp = t / WO;
    unsigned ho  = tmp % HO;
    tmp         /= HO;
    unsigned c   = tmp % CC;
    unsigned b   = tmp / CC;          // 0..15 (paired with b+16)

    float tp = temperature[(c * HO + ho) * WO + wo];
    tp = fmaxf(tp, 0.0f) + 0.1f;

    unsigned base = ((b * CC + c) * HH + 2u * ho) * WW + 2u * wo;
    float2 a0 = *reinterpret_cast<const float2*>(x + base);
    float2 a1 = *reinterpret_cast<const float2*>(x + base + WW);
    float2 b0 = *reinterpret_cast<const float2*>(x + base + OFF2);
    float2 b1 = *reinterpret_cast<const float2*>(x + base + OFF2 + WW);

    float xs0[4] = {a0.x, a0.y, a1.x, a1.y};
    float xs1[4] = {b0.x, b0.y, b1.x, b1.y};

    const unsigned ctr0 = 4u * t;                       // patch t
    const unsigned ctr1 = 4u * t + 4u * (unsigned)HALF_P;  // patch t+HALF_P

    float best0 = -__int_as_float(0x7f800000), sel0 = 0.0f;
    float best1 = best0,                       sel1 = 0.0f;

    #pragma unroll
    for (int j = 0; j < 4; j++) {
        // Two independent threefry chains per iteration -> 2x ILP
        float g0 = gumbel_from_bits(threefry_bits(ctr0 + (unsigned)j));
        float g1 = gumbel_from_bits(threefry_bits(ctr1 + (unsigned)j));
        float v0 = __fdiv_rn(xs0[j], tp) + g0;
        float v1 = __fdiv_rn(xs1[j], tp) + g1;
        if (v0 > best0) { best0 = v0; sel0 = xs0[j]; }  // first-max wins ties
        if (v1 > best1) { best1 = v1; sel1 = xs1[j]; }
    }

    out[t] = sel0;
    out[t + HALF_P] = sel1;
}

extern "C" void kernel_launch(void* const* d_in, const int* in_sizes, int n_in,
                              void* d_out, int out_size) {
    const float* x    = (const float*)d_in[0];  // (32,128,112,112) f32
    const float* temp = (const float*)d_in[1];  // (128,56,56) f32
    float* out        = (float*)d_out;          // (32,128,56,56) f32
    (void)in_sizes; (void)n_in; (void)out_size;

    const int threads = 256;
    const int blocks  = (HALF_P + threads - 1) / threads;  // 25088
    tdgs_pool_kernel<<<blocks, threads>>>(x, temp, out);
}